// round 12
// baseline (speedup 1.0000x reference)
#include <cuda_runtime.h>
#include <cuda_fp16.h>
#include <cstdint>
#include <math.h>

#define D_MODEL 1024
#define NHEAD 16
#define HDIM 64
#define SEQ 2048
#define NBATCH 2
#define NROWS (NBATCH * SEQ)          // 4096
#define EPS_V 1e-6f
#define NSPLIT 8

typedef uint16_t u16;
typedef uint32_t u32;

// ---------------- scratch (device globals; no allocation allowed) -----------
__device__ float g_q[NROWS * D_MODEL];
__device__ float g_k[NROWS * D_MODEL];
__device__ float g_v[NROWS * D_MODEL];
__device__ float g_kv[NBATCH * NHEAD * HDIM * HDIM];
__device__ float g_ksum[NBATCH * NHEAD * HDIM];
// split-K partials (no atomics)
__device__ float g_kvp[NSPLIT * NBATCH * NHEAD * HDIM * HDIM];
__device__ float g_ksump[NSPLIT * NBATCH * NHEAD * HDIM];

// fp16 planes
__device__ __align__(16) u16 g_xh[NROWS * D_MODEL];
__device__ __align__(16) u16 g_oh[NROWS * D_MODEL];
// packed weights: rows [0,1024)=wq, [1024,2048)=wk, [2048,3072)=wv, [3072,4096)=wo
__device__ __align__(16) u16 g_wh[4 * D_MODEL * D_MODEL];

__device__ __forceinline__ u32 smem_u32(const void* p) {
    u32 a;
    asm("{ .reg .u64 t; cvta.to.shared.u64 t, %1; cvt.u32.u64 %0, t; }"
        : "=r"(a) : "l"(p));
    return a;
}

__device__ __forceinline__ void ldsm4(u32* r, u32 addr) {
    asm volatile("ldmatrix.sync.aligned.m8n8.x4.shared.b16 {%0,%1,%2,%3}, [%4];"
                 : "=r"(r[0]), "=r"(r[1]), "=r"(r[2]), "=r"(r[3]) : "r"(addr));
}

__device__ __forceinline__ void mma16816h(float* c, const u32* a, u32 b0, u32 b1) {
    asm volatile(
        "mma.sync.aligned.m16n8k16.row.col.f32.f16.f16.f32 "
        "{%0,%1,%2,%3}, {%4,%5,%6,%7}, {%8,%9}, {%0,%1,%2,%3};"
        : "+f"(c[0]), "+f"(c[1]), "+f"(c[2]), "+f"(c[3])
        : "r"(a[0]), "r"(a[1]), "r"(a[2]), "r"(a[3]), "r"(b0), "r"(b1));
}

#define CP16(dst, src) \
    asm volatile("cp.async.cg.shared.global [%0], [%1], 16;" :: "r"(dst), "l"(src))
#define CP_COMMIT() asm volatile("cp.async.commit_group;" ::: "memory")
#define CP_WAIT0()  asm volatile("cp.async.wait_group 0;" ::: "memory")
#define CP_WAIT1()  asm volatile("cp.async.wait_group 1;" ::: "memory")

__device__ __forceinline__ uint2 cvt4h(float4 f) {
    half2 a = __floats2half2_rn(f.x, f.y);
    half2 b = __floats2half2_rn(f.z, f.w);
    return make_uint2(*(u32*)&a, *(u32*)&b);
}

// ---------------- fused conversion pass --------------------------------------
// jobs: [0, 1M) -> x (1M float4), [1M, 2M) -> packed weights (4 x 256K float4)
__global__ __launch_bounds__(256) void conv_all_kernel(
    const float* __restrict__ x,
    const float* __restrict__ w0, const float* __restrict__ w1,
    const float* __restrict__ w2, const float* __restrict__ w3)
{
    const u32 i = blockIdx.x * 256 + threadIdx.x;
    const u32 XQ = NROWS * D_MODEL / 4;                 // 1M float4
    if (i < XQ) {
        ((uint2*)g_xh)[i] = cvt4h(((const float4*)x)[i]);
    } else {
        const u32 j = i - XQ;
        const u32 m = j >> 18;                          // 256K float4 per weight
        const u32 e = j & 0x3FFFF;
        const float* src = (m == 0) ? w0 : (m == 1) ? w1 : (m == 2) ? w2 : w3;
        ((uint2*)g_wh)[((size_t)m << 18) + e] = cvt4h(((const float4*)src)[e]);
    }
}

// ======================= fp16 GEMM ==========================================
// C[M,Nseg] = Ah[M,K] @ Wh[N,K]^T + bias  (fp16 x fp16, fp32 acc)
// BM=BN=128. 8 warps in 4M x 2N, warp tile 32x64. acc=64 regs/thread.
// 3-stage cp.async, stage = 32KB, total 96KB -> 2 CTAs/SM.
// Warp-rotated ks order decorrelates smem/tensor phases across warps.
#define BM 128
#define BN 128
#define PLANE_B 16384
#define STAGE_B (2 * PLANE_B)                // 32768
#define GEMM_SMEM (3 * STAGE_B)              // 98304

__global__ __launch_bounds__(256, 2)
void gemm1t(const u16* __restrict__ Ah, const u16* __restrict__ Wh,
            const float* __restrict__ b0, const float* __restrict__ b1,
            const float* __restrict__ b2,
            float* __restrict__ C0, float* __restrict__ C1, float* __restrict__ C2,
            int M, int K, int actmask)
{
    extern __shared__ __align__(1024) char smem[];
    const u32 sb = smem_u32(smem);

    const int tid = threadIdx.x;
    const int lane = tid & 31, wid = tid >> 5;
    const int wm = wid >> 1, wn = wid & 1;        // 4M x 2N warp grid
    const int bm = blockIdx.y * BM;
    const int bng = blockIdx.x * BN;              // global col in packed weight
    const int seg = blockIdx.x >> 3;              // 1024/BN = 8 tiles per segment
    const int bns = bng & 1023;                   // col within segment

    const float* bias = (seg == 0) ? b0 : (seg == 1) ? b1 : b2;
    float* C = (seg == 0) ? C0 : (seg == 1) ? C1 : C2;
    const int act = (actmask >> seg) & 1;

    const int NCH = K / 64;

    // ---- ldmatrix addressing ----
    const int arow_l = (lane & 15);
    const u32 akb = (u32)((lane >> 4) * 16);
    const int brow_l = (lane & 7) + ((lane >> 4) << 3);
    const u32 bkb = (u32)(((lane >> 3) & 1) * 16);

    u32 abase[2], axor[2];
#pragma unroll
    for (int mt = 0; mt < 2; ++mt) {
        const int r = wm * 32 + mt * 16 + arow_l;
        abase[mt] = (u32)(r * 128);
        axor[mt] = (u32)((r & 7) << 4);
    }
    u32 bbase[4], bxor[4];
#pragma unroll
    for (int p = 0; p < 4; ++p) {
        const int r = wn * 64 + p * 16 + brow_l;
        bbase[p] = (u32)(r * 128);
        bxor[p] = (u32)((r & 7) << 4);
    }

    float acc[2][8][4];
#pragma unroll
    for (int i = 0; i < 2; ++i)
#pragma unroll
        for (int j = 0; j < 8; ++j)
#pragma unroll
            for (int d = 0; d < 4; ++d) acc[i][j][d] = 0.f;

    auto load_chunk = [&](int c, int stage) {
        const u32 bufb = sb + stage * STAGE_B;
        const size_t kc = (size_t)c * 64;
#pragma unroll
        for (int i = 0; i < 4; ++i) {
            const int idx = i * 256 + tid;
            const int r = idx >> 3, c16 = idx & 7;
            const u32 dsto = (u32)(r * 128 + ((c16 * 16) ^ ((r & 7) * 16)));
            const size_t asrc = (size_t)(bm + r) * K + kc + c16 * 8;
            const size_t wsrc = (size_t)(bng + r) * K + kc + c16 * 8;
            CP16(bufb + dsto, Ah + asrc);
            CP16(bufb + PLANE_B + dsto, Wh + wsrc);
        }
        CP_COMMIT();
    };

    load_chunk(0, 0);
    load_chunk(1, 1);

    int stage = 0;
    for (int c = 0; c < NCH; ++c) {
        if (c == NCH - 1) { CP_WAIT0(); } else { CP_WAIT1(); }
        __syncthreads();
        if (c + 2 < NCH) {
            int s2 = stage + 2; if (s2 >= 3) s2 -= 3;
            load_chunk(c + 2, s2);
        }

        const u32 bufb = sb + stage * STAGE_B;
        const u32 AHb = bufb, WHb = bufb + PLANE_B;

#pragma unroll
        for (int kk = 0; kk < 4; ++kk) {
            const int ks = (kk + wid) & 3;          // warp-rotated phase
            u32 ah[2][4], bh[4][4];
#pragma unroll
            for (int mt = 0; mt < 2; ++mt) {
                const u32 t = ((u32)(ks * 32) + akb) ^ axor[mt];
                ldsm4(ah[mt], AHb + abase[mt] + t);
            }
#pragma unroll
            for (int p = 0; p < 4; ++p) {
                const u32 t = ((u32)(ks * 32) + bkb) ^ bxor[p];
                ldsm4(bh[p], WHb + bbase[p] + t);
            }
#pragma unroll
            for (int mt = 0; mt < 2; ++mt)
#pragma unroll
                for (int nt = 0; nt < 8; ++nt) {
                    const int p = nt >> 1, q = (nt & 1) * 2;
                    mma16816h(acc[mt][nt], ah[mt], bh[p][q], bh[p][q + 1]);
                }
        }
        ++stage; if (stage == 3) stage = 0;
    }

    // ---- epilogue ----
    const int erow = bm + wm * 32 + (lane >> 2);
    const int ecol0 = bns + wn * 64 + (lane & 3) * 2;
#pragma unroll
    for (int nt = 0; nt < 8; ++nt) {
        const int col = ecol0 + nt * 8;
        const float bb0 = bias[col], bb1 = bias[col + 1];
#pragma unroll
        for (int mt = 0; mt < 2; ++mt) {
#pragma unroll
            for (int h = 0; h < 2; ++h) {
                const int row = erow + mt * 16 + h * 8;
                float v0 = acc[mt][nt][2 * h] + bb0;
                float v1 = acc[mt][nt][2 * h + 1] + bb1;
                if (act) {
                    v0 = (v0 > 0.f) ? (v0 + 1.f) : __expf(v0);
                    v1 = (v1 > 0.f) ? (v1 + 1.f) : __expf(v1);
                }
                *(float2*)(C + (size_t)row * D_MODEL + col) = make_float2(v0, v1);
            }
        }
    }
}

// ---------------- kv partials: kf^T @ v per (b,h,split), no atomics ---------
__global__ __launch_bounds__(256)
void kv_kernel()
{
    const int bh = blockIdx.x;
    const int split = blockIdx.y;
    const int b = bh >> 4, h = bh & 15;
    const int j0 = b * SEQ + split * 256;

    const float* Kp = g_k + (size_t)j0 * D_MODEL + h * HDIM;
    const float* Vp = g_v + (size_t)j0 * D_MODEL + h * HDIM;

    __shared__ __align__(16) float ks[32][64];
    __shared__ __align__(16) float vs[32][64];

    const int tid = threadIdx.x;
    const int eg = tid & 15, dg = tid >> 4;
    const int e0 = eg * 4, d0 = dg * 4;

    float acc[4][4];
#pragma unroll
    for (int i = 0; i < 4; ++i)
#pragma unroll
        for (int j = 0; j < 4; ++j) acc[i][j] = 0.f;
    float sacc[4] = {0.f, 0.f, 0.f, 0.f};

    for (int it = 0; it < 8; ++it) {
        const int rbase = it * 32;
#pragma unroll
        for (int i = 0; i < 2; ++i) {
            const int idx = i * 256 + tid;
            const int r = idx >> 4, cc = (idx & 15) * 4;
            *(float4*)&ks[r][cc] = *(const float4*)(Kp + (size_t)(rbase + r) * D_MODEL + cc);
            *(float4*)&vs[r][cc] = *(const float4*)(Vp + (size_t)(rbase + r) * D_MODEL + cc);
        }
        __syncthreads();
#pragma unroll
        for (int r = 0; r < 32; ++r) {
            float4 kd4 = *(const float4*)&ks[r][d0];
            float4 ve4 = *(const float4*)&vs[r][e0];
            float kd[4] = {kd4.x, kd4.y, kd4.z, kd4.w};
            float ve[4] = {ve4.x, ve4.y, ve4.z, ve4.w};
#pragma unroll
            for (int i = 0; i < 4; ++i)
#pragma unroll
                for (int j = 0; j < 4; ++j)
                    acc[i][j] = fmaf(kd[i], ve[j], acc[i][j]);
            if (eg == 0) {
#pragma unroll
                for (int i = 0; i < 4; ++i) sacc[i] += kd[i];
            }
        }
        __syncthreads();
    }

    float* kvp = g_kvp + ((size_t)split * 32 + bh) * (HDIM * HDIM);
#pragma unroll
    for (int i = 0; i < 4; ++i)
        *(float4*)&kvp[(d0 + i) * HDIM + e0] =
            make_float4(acc[i][0], acc[i][1], acc[i][2], acc[i][3]);
    if (eg == 0) {
#pragma unroll
        for (int i = 0; i < 4; ++i)
            g_ksump[((size_t)split * 32 + bh) * HDIM + d0 + i] = sacc[i];
    }
}

// ---------------- reduce split partials --------------------------------------
__global__ __launch_bounds__(256)
void reduce_kv_kernel()
{
    const int bh = blockIdx.x;
    const int tid = threadIdx.x;
    // 4096 floats = 1024 float4; 256 threads x 4
#pragma unroll
    for (int i = 0; i < 4; ++i) {
        const int e = i * 256 + tid;
        float4 s = make_float4(0.f, 0.f, 0.f, 0.f);
#pragma unroll
        for (int p = 0; p < NSPLIT; ++p) {
            float4 v = ((const float4*)(g_kvp + ((size_t)p * 32 + bh) * 4096))[e];
            s.x += v.x; s.y += v.y; s.z += v.z; s.w += v.w;
        }
        ((float4*)(g_kv + (size_t)bh * 4096))[e] = s;
    }
    if (tid < HDIM) {
        float s = 0.f;
#pragma unroll
        for (int p = 0; p < NSPLIT; ++p)
            s += g_ksump[((size_t)p * 32 + bh) * HDIM + tid];
        g_ksum[bh * HDIM + tid] = s;
    }
}

// ---------------- attended = (qf @ kv) / max(qf . ksum, eps) -----------------
__global__ __launch_bounds__(256)
void attend_kernel()
{
    const int tile = blockIdx.x;
    const int bh = blockIdx.y;
    const int b = bh >> 4, h = bh & 15;
    const int row0 = b * SEQ + tile * 64;

    __shared__ __align__(16) float kvs[64][64];
    __shared__ __align__(16) float qs[64][64];
    __shared__ float ksum_s[64];

    const int tid = threadIdx.x;

    const float* kvp = g_kv + (size_t)bh * HDIM * HDIM;
    for (int i = tid; i < 1024; i += 256)
        ((float4*)kvs)[i] = ((const float4*)kvp)[i];
    if (tid < 64) ksum_s[tid] = g_ksum[bh * HDIM + tid];

    const float* Qp = g_q + (size_t)row0 * D_MODEL + h * HDIM;
    for (int i = tid; i < 1024; i += 256) {
        const int r = i >> 4, c = (i & 15) * 4;
        *(float4*)&qs[r][c] = *(const float4*)(Qp + (size_t)r * D_MODEL + c);
    }
    __syncthreads();

    const int cg = tid & 15, rg = tid >> 4;
    const int c0 = cg * 4, r0 = rg * 4;

    float num[4][4];
#pragma unroll
    for (int i = 0; i < 4; ++i)
#pragma unroll
        for (int j = 0; j < 4; ++j) num[i][j] = 0.f;
    float den[4] = {0.f, 0.f, 0.f, 0.f};

    for (int d = 0; d < 64; ++d) {
        float qv[4];
#pragma unroll
        for (int i = 0; i < 4; ++i) qv[i] = qs[r0 + i][d];
        float4 kv4 = *(const float4*)&kvs[d][c0];
        float kva[4] = {kv4.x, kv4.y, kv4.z, kv4.w};
        const float kd = ksum_s[d];
#pragma unroll
        for (int i = 0; i < 4; ++i) {
#pragma unroll
            for (int j = 0; j < 4; ++j)
                num[i][j] = fmaf(qv[i], kva[j], num[i][j]);
            den[i] = fmaf(qv[i], kd, den[i]);
        }
    }

#pragma unroll
    for (int i = 0; i < 4; ++i) {
        const float inv = 1.f / fmaxf(den[i], EPS_V);
        float4 res = make_float4(num[i][0] * inv, num[i][1] * inv,
                                 num[i][2] * inv, num[i][3] * inv);
        const size_t e4 = ((size_t)(row0 + r0 + i) * D_MODEL + h * HDIM + c0) >> 2;
        ((uint2*)g_oh)[e4] = cvt4h(res);
    }
}

// ---------------- launch -----------------------------------------------------
extern "C" void kernel_launch(void* const* d_in, const int* in_sizes, int n_in,
                              void* d_out, int out_size)
{
    const float* x  = (const float*)d_in[0];
    const float* wq = (const float*)d_in[1];
    const float* bq = (const float*)d_in[2];
    const float* wk = (const float*)d_in[3];
    const float* bk = (const float*)d_in[4];
    const float* wv = (const float*)d_in[5];
    const float* bv = (const float*)d_in[6];
    const float* wo = (const float*)d_in[7];
    const float* bo = (const float*)d_in[8];
    float* out = (float*)d_out;

    const int M = in_sizes[0] / D_MODEL;   // 4096

    float *qp, *kp, *vp;
    u16 *xh, *oh, *wh;
    cudaGetSymbolAddress((void**)&qp, g_q);
    cudaGetSymbolAddress((void**)&kp, g_k);
    cudaGetSymbolAddress((void**)&vp, g_v);
    cudaGetSymbolAddress((void**)&xh, g_xh);
    cudaGetSymbolAddress((void**)&oh, g_oh);
    cudaGetSymbolAddress((void**)&wh, g_wh);

    cudaFuncSetAttribute(gemm1t, cudaFuncAttributeMaxDynamicSharedMemorySize, GEMM_SMEM);

    // 1: fused conversion (x + all weights): 2M float4 jobs
    conv_all_kernel<<<(2 * 1024 * 1024) / 256, 256>>>(x, wq, wk, wv, wo);

    // 2: fused QKV projection, N=3072 over packed weights
    gemm1t<<<dim3(3 * D_MODEL / BN, M / BM), 256, GEMM_SMEM>>>(
        xh, wh,
        bq, bk, bv, qp, kp, vp,
        M, D_MODEL, 0b011);

    // 3,4,5: linear-attention middle (no atomics)
    kv_kernel<<<dim3(NBATCH * NHEAD, NSPLIT), 256>>>();
    reduce_kv_kernel<<<NBATCH * NHEAD, 256>>>();
    attend_kernel<<<dim3(SEQ / 64, NBATCH * NHEAD), 256>>>();

    // 6: output projection (wo rows start at 3*D*D)
    gemm1t<<<dim3(D_MODEL / BN, M / BM), 256, GEMM_SMEM>>>(
        oh, wh + (size_t)3 * D_MODEL * D_MODEL,
        bo, bo, bo, out, out, out,
        M, D_MODEL, 0);
}

// round 13
// speedup vs baseline: 1.0539x; 1.0539x over previous
#include <cuda_runtime.h>
#include <cuda_fp16.h>
#include <cstdint>
#include <math.h>

#define D_MODEL 1024
#define NHEAD 16
#define HDIM 64
#define SEQ 2048
#define NBATCH 2
#define NROWS (NBATCH * SEQ)          // 4096
#define EPS_V 1e-6f

typedef uint16_t u16;
typedef uint32_t u32;

// ---------------- scratch (device globals; no allocation allowed) -----------
__device__ float g_kv[NBATCH * NHEAD * HDIM * HDIM];
__device__ float g_ksum[NBATCH * NHEAD * HDIM];

// fp16 planes
__device__ __align__(16) u16 g_xh[NROWS * D_MODEL];
__device__ __align__(16) u16 g_qh[NROWS * D_MODEL];
__device__ __align__(16) u16 g_kh[NROWS * D_MODEL];
__device__ __align__(16) u16 g_vh[NROWS * D_MODEL];
__device__ __align__(16) u16 g_oh[NROWS * D_MODEL];
// packed weights: rows [0,1024)=wq, [1024,2048)=wk, [2048,3072)=wv, [3072,4096)=wo
__device__ __align__(16) u16 g_wh[4 * D_MODEL * D_MODEL];

__device__ __forceinline__ u32 smem_u32(const void* p) {
    u32 a;
    asm("{ .reg .u64 t; cvta.to.shared.u64 t, %1; cvt.u32.u64 %0, t; }"
        : "=r"(a) : "l"(p));
    return a;
}

__device__ __forceinline__ void ldsm4(u32* r, u32 addr) {
    asm volatile("ldmatrix.sync.aligned.m8n8.x4.shared.b16 {%0,%1,%2,%3}, [%4];"
                 : "=r"(r[0]), "=r"(r[1]), "=r"(r[2]), "=r"(r[3]) : "r"(addr));
}

__device__ __forceinline__ void mma16816h(float* c, const u32* a, u32 b0, u32 b1) {
    asm volatile(
        "mma.sync.aligned.m16n8k16.row.col.f32.f16.f16.f32 "
        "{%0,%1,%2,%3}, {%4,%5,%6,%7}, {%8,%9}, {%0,%1,%2,%3};"
        : "+f"(c[0]), "+f"(c[1]), "+f"(c[2]), "+f"(c[3])
        : "r"(a[0]), "r"(a[1]), "r"(a[2]), "r"(a[3]), "r"(b0), "r"(b1));
}

#define CP16(dst, src) \
    asm volatile("cp.async.cg.shared.global [%0], [%1], 16;" :: "r"(dst), "l"(src))
#define CP_COMMIT() asm volatile("cp.async.commit_group;" ::: "memory")
#define CP_WAIT0()  asm volatile("cp.async.wait_group 0;" ::: "memory")
#define CP_WAIT1()  asm volatile("cp.async.wait_group 1;" ::: "memory")

__device__ __forceinline__ uint2 cvt4h(float4 f) {
    half2 a = __floats2half2_rn(f.x, f.y);
    half2 b = __floats2half2_rn(f.z, f.w);
    return make_uint2(*(u32*)&a, *(u32*)&b);
}

// convert 8 halves (uint4) -> 8 floats
__device__ __forceinline__ void h8_to_f8(uint4 v, float* o) {
    float2 f0 = __half22float2(*(half2*)&v.x);
    float2 f1 = __half22float2(*(half2*)&v.y);
    float2 f2 = __half22float2(*(half2*)&v.z);
    float2 f3 = __half22float2(*(half2*)&v.w);
    o[0] = f0.x; o[1] = f0.y; o[2] = f1.x; o[3] = f1.y;
    o[4] = f2.x; o[5] = f2.y; o[6] = f3.x; o[7] = f3.y;
}

// ---------------- fused conversion pass --------------------------------------
__global__ __launch_bounds__(256) void conv_all_kernel(
    const float* __restrict__ x,
    const float* __restrict__ w0, const float* __restrict__ w1,
    const float* __restrict__ w2, const float* __restrict__ w3)
{
    const u32 i = blockIdx.x * 256 + threadIdx.x;
    const u32 XQ = NROWS * D_MODEL / 4;                 // 1M float4
    if (i < XQ) {
        ((uint2*)g_xh)[i] = cvt4h(((const float4*)x)[i]);
    } else {
        const u32 j = i - XQ;
        const u32 m = j >> 18;                          // 256K float4 per weight
        const u32 e = j & 0x3FFFF;
        const float* src = (m == 0) ? w0 : (m == 1) ? w1 : (m == 2) ? w2 : w3;
        ((uint2*)g_wh)[((size_t)m << 18) + e] = cvt4h(((const float4*)src)[e]);
    }
}

// ---------------- zero the kv / ksum accumulators ---------------------------
__global__ void zero_kv_kernel()
{
    const int i = blockIdx.x * blockDim.x + threadIdx.x;
    if (i < NBATCH * NHEAD * HDIM * HDIM) g_kv[i] = 0.f;
    if (i < NBATCH * NHEAD * HDIM)        g_ksum[i] = 0.f;
}

// ======================= fp16 GEMM ==========================================
// C[M,Nseg] = Ah[M,K] @ Wh[N,K]^T + bias  (fp16 x fp16, fp32 acc)
// BM=BN=128. 8 warps in 4M x 2N, warp tile 32x64. acc=64 regs/thread.
// 3-stage cp.async, stage = 32KB, total 96KB -> 2 CTAs/SM.
// OUT16: store half2 planes (QKV path); else fp32 (final output).
#define BM 128
#define BN 128
#define PLANE_B 16384
#define STAGE_B (2 * PLANE_B)                // 32768
#define GEMM_SMEM (3 * STAGE_B)              // 98304

template <int OUT16>
__global__ __launch_bounds__(256, 2)
void gemm1t(const u16* __restrict__ Ah, const u16* __restrict__ Wh,
            const float* __restrict__ b0, const float* __restrict__ b1,
            const float* __restrict__ b2,
            void* __restrict__ C0, void* __restrict__ C1, void* __restrict__ C2,
            int M, int K, int actmask)
{
    extern __shared__ __align__(1024) char smem[];
    const u32 sb = smem_u32(smem);

    const int tid = threadIdx.x;
    const int lane = tid & 31, wid = tid >> 5;
    const int wm = wid >> 1, wn = wid & 1;        // 4M x 2N warp grid
    const int bm = blockIdx.y * BM;
    const int bng = blockIdx.x * BN;              // global col in packed weight
    const int seg = blockIdx.x >> 3;              // 1024/BN = 8 tiles per segment
    const int bns = bng & 1023;                   // col within segment

    const float* bias = (seg == 0) ? b0 : (seg == 1) ? b1 : b2;
    void* C = (seg == 0) ? C0 : (seg == 1) ? C1 : C2;
    const int act = (actmask >> seg) & 1;

    const int NCH = K / 64;

    // ---- ldmatrix addressing ----
    const int arow_l = (lane & 15);
    const u32 akb = (u32)((lane >> 4) * 16);
    const int brow_l = (lane & 7) + ((lane >> 4) << 3);
    const u32 bkb = (u32)(((lane >> 3) & 1) * 16);

    u32 abase[2], axor[2];
#pragma unroll
    for (int mt = 0; mt < 2; ++mt) {
        const int r = wm * 32 + mt * 16 + arow_l;
        abase[mt] = (u32)(r * 128);
        axor[mt] = (u32)((r & 7) << 4);
    }
    u32 bbase[4], bxor[4];
#pragma unroll
    for (int p = 0; p < 4; ++p) {
        const int r = wn * 64 + p * 16 + brow_l;
        bbase[p] = (u32)(r * 128);
        bxor[p] = (u32)((r & 7) << 4);
    }

    float acc[2][8][4];
#pragma unroll
    for (int i = 0; i < 2; ++i)
#pragma unroll
        for (int j = 0; j < 8; ++j)
#pragma unroll
            for (int d = 0; d < 4; ++d) acc[i][j][d] = 0.f;

    auto load_chunk = [&](int c, int stage) {
        const u32 bufb = sb + stage * STAGE_B;
        const size_t kc = (size_t)c * 64;
#pragma unroll
        for (int i = 0; i < 4; ++i) {
            const int idx = i * 256 + tid;
            const int r = idx >> 3, c16 = idx & 7;
            const u32 dsto = (u32)(r * 128 + ((c16 * 16) ^ ((r & 7) * 16)));
            const size_t asrc = (size_t)(bm + r) * K + kc + c16 * 8;
            const size_t wsrc = (size_t)(bng + r) * K + kc + c16 * 8;
            CP16(bufb + dsto, Ah + asrc);
            CP16(bufb + PLANE_B + dsto, Wh + wsrc);
        }
        CP_COMMIT();
    };

    load_chunk(0, 0);
    load_chunk(1, 1);

    int stage = 0;
    for (int c = 0; c < NCH; ++c) {
        if (c == NCH - 1) { CP_WAIT0(); } else { CP_WAIT1(); }
        __syncthreads();
        if (c + 2 < NCH) {
            int s2 = stage + 2; if (s2 >= 3) s2 -= 3;
            load_chunk(c + 2, s2);
        }

        const u32 bufb = sb + stage * STAGE_B;
        const u32 AHb = bufb, WHb = bufb + PLANE_B;

#pragma unroll
        for (int ks = 0; ks < 4; ++ks) {
            u32 ah[2][4], bh[4][4];
#pragma unroll
            for (int mt = 0; mt < 2; ++mt) {
                const u32 t = ((u32)(ks * 32) + akb) ^ axor[mt];
                ldsm4(ah[mt], AHb + abase[mt] + t);
            }
#pragma unroll
            for (int p = 0; p < 4; ++p) {
                const u32 t = ((u32)(ks * 32) + bkb) ^ bxor[p];
                ldsm4(bh[p], WHb + bbase[p] + t);
            }
#pragma unroll
            for (int mt = 0; mt < 2; ++mt)
#pragma unroll
                for (int nt = 0; nt < 8; ++nt) {
                    const int p = nt >> 1, q = (nt & 1) * 2;
                    mma16816h(acc[mt][nt], ah[mt], bh[p][q], bh[p][q + 1]);
                }
        }
        ++stage; if (stage == 3) stage = 0;
    }

    // ---- epilogue ----
    const int erow = bm + wm * 32 + (lane >> 2);
    const int ecol0 = bns + wn * 64 + (lane & 3) * 2;
#pragma unroll
    for (int nt = 0; nt < 8; ++nt) {
        const int col = ecol0 + nt * 8;
        const float bb0 = bias[col], bb1 = bias[col + 1];
#pragma unroll
        for (int mt = 0; mt < 2; ++mt) {
#pragma unroll
            for (int h = 0; h < 2; ++h) {
                const int row = erow + mt * 16 + h * 8;
                float v0 = acc[mt][nt][2 * h] + bb0;
                float v1 = acc[mt][nt][2 * h + 1] + bb1;
                if (act) {
                    v0 = (v0 > 0.f) ? (v0 + 1.f) : __expf(v0);
                    v1 = (v1 > 0.f) ? (v1 + 1.f) : __expf(v1);
                }
                if (OUT16) {
                    half2 hp = __floats2half2_rn(v0, v1);
                    *(u32*)((u16*)C + (size_t)row * D_MODEL + col) = *(u32*)&hp;
                } else {
                    *(float2*)((float*)C + (size_t)row * D_MODEL + col) =
                        make_float2(v0, v1);
                }
            }
        }
    }
}

// ---------------- kv = kf^T @ v per (b,h), split-K over sequence ------------
// fp16 inputs, fp32 compute. 32-row tiles.
__global__ __launch_bounds__(256)
void kv_kernel()
{
    const int bh = blockIdx.x;
    const int split = blockIdx.y;
    const int b = bh >> 4, h = bh & 15;
    const int j0 = b * SEQ + split * 256;

    const u16* Kp = g_kh + (size_t)j0 * D_MODEL + h * HDIM;
    const u16* Vp = g_vh + (size_t)j0 * D_MODEL + h * HDIM;

    __shared__ __align__(16) float ks[32][64];
    __shared__ __align__(16) float vs[32][64];

    const int tid = threadIdx.x;
    const int eg = tid & 15, dg = tid >> 4;
    const int e0 = eg * 4, d0 = dg * 4;

    float acc[4][4];
#pragma unroll
    for (int i = 0; i < 4; ++i)
#pragma unroll
        for (int j = 0; j < 4; ++j) acc[i][j] = 0.f;
    float sacc[4] = {0.f, 0.f, 0.f, 0.f};

    for (int it = 0; it < 8; ++it) {
        const int rbase = it * 32;
        // 32 rows x 64 halves = 256 uint4-chunks per tensor; thread t -> chunk t
        {
            const int r = tid >> 3, c8 = (tid & 7) * 8;
            float tmp[8];
            uint4 kd = *(const uint4*)(Kp + (size_t)(rbase + r) * D_MODEL + c8);
            h8_to_f8(kd, tmp);
#pragma unroll
            for (int j = 0; j < 8; ++j) ks[r][c8 + j] = tmp[j];
            uint4 vd = *(const uint4*)(Vp + (size_t)(rbase + r) * D_MODEL + c8);
            h8_to_f8(vd, tmp);
#pragma unroll
            for (int j = 0; j < 8; ++j) vs[r][c8 + j] = tmp[j];
        }
        __syncthreads();
#pragma unroll
        for (int r = 0; r < 32; ++r) {
            float4 kd4 = *(const float4*)&ks[r][d0];
            float4 ve4 = *(const float4*)&vs[r][e0];
            float kd[4] = {kd4.x, kd4.y, kd4.z, kd4.w};
            float ve[4] = {ve4.x, ve4.y, ve4.z, ve4.w};
#pragma unroll
            for (int i = 0; i < 4; ++i)
#pragma unroll
                for (int j = 0; j < 4; ++j)
                    acc[i][j] = fmaf(kd[i], ve[j], acc[i][j]);
            if (eg == 0) {
#pragma unroll
                for (int i = 0; i < 4; ++i) sacc[i] += kd[i];
            }
        }
        __syncthreads();
    }

    float* kvp = g_kv + (size_t)bh * HDIM * HDIM;
#pragma unroll
    for (int i = 0; i < 4; ++i)
#pragma unroll
        for (int j = 0; j < 4; ++j)
            atomicAdd(&kvp[(d0 + i) * HDIM + e0 + j], acc[i][j]);
    if (eg == 0) {
#pragma unroll
        for (int i = 0; i < 4; ++i)
            atomicAdd(&g_ksum[bh * HDIM + d0 + i], sacc[i]);
    }
}

// ---------------- attended = (qf @ kv) / max(qf . ksum, eps) -----------------
__global__ __launch_bounds__(256)
void attend_kernel()
{
    const int tile = blockIdx.x;
    const int bh = blockIdx.y;
    const int b = bh >> 4, h = bh & 15;
    const int row0 = b * SEQ + tile * 64;

    __shared__ __align__(16) float kvs[64][64];
    __shared__ __align__(16) float qs[64][64];
    __shared__ float ksum_s[64];

    const int tid = threadIdx.x;

    const float* kvp = g_kv + (size_t)bh * HDIM * HDIM;
    for (int i = tid; i < 1024; i += 256)
        ((float4*)kvs)[i] = ((const float4*)kvp)[i];
    if (tid < 64) ksum_s[tid] = g_ksum[bh * HDIM + tid];

    const u16* Qp = g_qh + (size_t)row0 * D_MODEL + h * HDIM;
    // 64 rows x 64 halves = 512 uint4-chunks; 256 threads x 2
#pragma unroll
    for (int i = 0; i < 2; ++i) {
        const int idx = i * 256 + tid;
        const int r = idx >> 3, c8 = (idx & 7) * 8;
        float tmp[8];
        uint4 qd = *(const uint4*)(Qp + (size_t)r * D_MODEL + c8);
        h8_to_f8(qd, tmp);
#pragma unroll
        for (int j = 0; j < 8; ++j) qs[r][c8 + j] = tmp[j];
    }
    __syncthreads();

    const int cg = tid & 15, rg = tid >> 4;
    const int c0 = cg * 4, r0 = rg * 4;

    float num[4][4];
#pragma unroll
    for (int i = 0; i < 4; ++i)
#pragma unroll
        for (int j = 0; j < 4; ++j) num[i][j] = 0.f;
    float den[4] = {0.f, 0.f, 0.f, 0.f};

    for (int d = 0; d < 64; ++d) {
        float qv[4];
#pragma unroll
        for (int i = 0; i < 4; ++i) qv[i] = qs[r0 + i][d];
        float4 kv4 = *(const float4*)&kvs[d][c0];
        float kva[4] = {kv4.x, kv4.y, kv4.z, kv4.w};
        const float kd = ksum_s[d];
#pragma unroll
        for (int i = 0; i < 4; ++i) {
#pragma unroll
            for (int j = 0; j < 4; ++j)
                num[i][j] = fmaf(qv[i], kva[j], num[i][j]);
            den[i] = fmaf(qv[i], kd, den[i]);
        }
    }

#pragma unroll
    for (int i = 0; i < 4; ++i) {
        const float inv = 1.f / fmaxf(den[i], EPS_V);
        float4 res = make_float4(num[i][0] * inv, num[i][1] * inv,
                                 num[i][2] * inv, num[i][3] * inv);
        const size_t e4 = ((size_t)(row0 + r0 + i) * D_MODEL + h * HDIM + c0) >> 2;
        ((uint2*)g_oh)[e4] = cvt4h(res);
    }
}

// ---------------- launch -----------------------------------------------------
extern "C" void kernel_launch(void* const* d_in, const int* in_sizes, int n_in,
                              void* d_out, int out_size)
{
    const float* x  = (const float*)d_in[0];
    const float* wq = (const float*)d_in[1];
    const float* bq = (const float*)d_in[2];
    const float* wk = (const float*)d_in[3];
    const float* bk = (const float*)d_in[4];
    const float* wv = (const float*)d_in[5];
    const float* bv = (const float*)d_in[6];
    const float* wo = (const float*)d_in[7];
    const float* bo = (const float*)d_in[8];
    float* out = (float*)d_out;

    const int M = in_sizes[0] / D_MODEL;   // 4096

    u16 *xh, *qh, *kh, *vh, *oh, *wh;
    cudaGetSymbolAddress((void**)&xh, g_xh);
    cudaGetSymbolAddress((void**)&qh, g_qh);
    cudaGetSymbolAddress((void**)&kh, g_kh);
    cudaGetSymbolAddress((void**)&vh, g_vh);
    cudaGetSymbolAddress((void**)&oh, g_oh);
    cudaGetSymbolAddress((void**)&wh, g_wh);

    cudaFuncSetAttribute(gemm1t<1>, cudaFuncAttributeMaxDynamicSharedMemorySize, GEMM_SMEM);
    cudaFuncSetAttribute(gemm1t<0>, cudaFuncAttributeMaxDynamicSharedMemorySize, GEMM_SMEM);

    // 1: fused conversion (x + all weights)
    conv_all_kernel<<<(2 * 1024 * 1024) / 256, 256>>>(x, wq, wk, wv, wo);
    // 2: zero accumulators
    zero_kv_kernel<<<(NBATCH * NHEAD * HDIM * HDIM + 255) / 256, 256>>>();

    // 3: fused QKV projection -> fp16 planes
    gemm1t<1><<<dim3(3 * D_MODEL / BN, M / BM), 256, GEMM_SMEM>>>(
        xh, wh,
        bq, bk, bv, qh, kh, vh,
        M, D_MODEL, 0b011);

    // 4,5: linear-attention middle
    kv_kernel<<<dim3(NBATCH * NHEAD, 8), 256>>>();
    attend_kernel<<<dim3(SEQ / 64, NBATCH * NHEAD), 256>>>();

    // 6: output projection (fp32 out)
    gemm1t<0><<<dim3(D_MODEL / BN, M / BM), 256, GEMM_SMEM>>>(
        oh, wh + (size_t)3 * D_MODEL * D_MODEL,
        bo, bo, bo, out, out, out,
        M, D_MODEL, 0);
}